// round 9
// baseline (speedup 1.0000x reference)
#include <cuda_runtime.h>
#include <cuda_fp16.h>
#include <math.h>

// ---------------- problem constants ----------------
#define NB   16
#define NC   128
#define NHC  512
#define HWSZ 4096

// ---------------- scratch ----------------
__device__ __half g_z[67108864];     // [E*B][C][HW] expert conv raw (fp16)
__device__ __half g_combp[8388608];  // [B][chunk8][px4096][16kp] fp16
__device__ __half g_h1[33554432];
__device__ float  g_h2[8388608];     // COMPACT [B][HC][32][32]
__device__ float  g_h3[2097152];
__device__ float  g_wts[128];
__device__ __half g_xr[8388608];     // [B][chunk8][h][w][16kp]
__device__ __half g_wr[1179648];     // [E][chunk8][tap9][oc128][16kp]
__device__ __half g_w1r[65536];      // [ht4][chunk8][hcl128][16kp]
__device__ float g_part_exp[1024 * 64 * 2];
__device__ float g_ms_exp[1024 * 2];
__device__ float g_part1[128 * 32 * 2];
__device__ float g_ms1[128 * 2];
__device__ float g_part2[128 * 64 * 2];
__device__ float g_ms2[128 * 2];
__device__ float g_part3[128 * 16 * 2];
__device__ float g_ms3[128 * 2];

__device__ __forceinline__ float silu_f(float x) {
    return x / (1.0f + __expf(-x));
}
// permuted k index: j in [0,16) -> k, so thread r's 4 contiguous halves are
// k = {2r, 2r+1, 2r+8, 2r+9}
__device__ __forceinline__ int kmap(int j) {
    return ((j >> 2) * 2) + (j & 1) + ((j >> 1) & 1) * 8;
}
__device__ __forceinline__ void cp16(unsigned s, const void* g, int sz) {
    asm volatile("cp.async.cg.shared.global [%0], [%1], 16, %2;\n"
                 :: "r"(s), "l"(g), "r"(sz) : "memory");
}
__device__ __forceinline__ void cp_commit() {
    asm volatile("cp.async.commit_group;\n" ::: "memory");
}
__device__ __forceinline__ void cp_wait1() {
    asm volatile("cp.async.wait_group 1;\n" ::: "memory");
}
__device__ __forceinline__ void mma16(float* c, unsigned a0, unsigned a1, unsigned a2,
                                      unsigned a3, unsigned b0, unsigned b1) {
    asm volatile("mma.sync.aligned.m16n8k16.row.col.f32.f16.f16.f32 "
                 "{%0,%1,%2,%3}, {%4,%5,%6,%7}, {%8,%9}, {%0,%1,%2,%3};"
                 : "+f"(c[0]), "+f"(c[1]), "+f"(c[2]), "+f"(c[3])
                 : "r"(a0), "r"(a1), "r"(a2), "r"(a3), "r"(b0), "r"(b1));
}

// ---------------- transforms (fp16 + permute) ----------
__global__ void k_xform_x(const float* __restrict__ x) {
    int idx = blockIdx.x * 256 + threadIdx.x;   // 524288
    int w = idx & 63, h = (idx >> 6) & 63, chunk = (idx >> 12) & 7, b = idx >> 15;
    __align__(16) __half o[16];
#pragma unroll
    for (int j = 0; j < 16; j++) {
        int c = chunk * 16 + kmap(j);
        o[j] = __float2half(x[((b * 128 + c) << 12) + (h << 6) + w]);
    }
    uint4* dst = (uint4*)(g_xr + (size_t)idx * 16);
    dst[0] = ((uint4*)o)[0];
    dst[1] = ((uint4*)o)[1];
}

__global__ void k_xform_w(const float* __restrict__ w_exp) {
    int idx = blockIdx.x * 256 + threadIdx.x;   // 73728
    int oc = idx & 127;
    int t2 = idx >> 7;
    int tap = t2 % 9, ec = t2 / 9;
    int chunk = ec & 7, e = ec >> 3;
    __align__(16) __half o[16];
#pragma unroll
    for (int j = 0; j < 16; j++) {
        int c = chunk * 16 + kmap(j);
        o[j] = __float2half(w_exp[((e * 128 + oc) * 128 + c) * 9 + tap]);
    }
    uint4* dst = (uint4*)(g_wr + (size_t)idx * 16);
    dst[0] = ((uint4*)o)[0];
    dst[1] = ((uint4*)o)[1];
}

__global__ void k_xform_w1(const float* __restrict__ w_pw1) {
    int idx = blockIdx.x * 256 + threadIdx.x;   // 4096
    int hcl = idx & 127, chunk = (idx >> 7) & 7, ht = idx >> 10;
    __align__(16) __half o[16];
#pragma unroll
    for (int j = 0; j < 16; j++) {
        int c = chunk * 16 + kmap(j);
        o[j] = __float2half(w_pw1[(ht * 128 + hcl) * 128 + c]);
    }
    uint4* dst = (uint4*)(g_w1r + (size_t)idx * 16);
    dst[0] = ((uint4*)o)[0];
    dst[1] = ((uint4*)o)[1];
}

// ---------------- router ----------------
__global__ void k_router(const float* __restrict__ w1, const float* __restrict__ b1,
                         const float* __restrict__ w2, const float* __restrict__ b2) {
    __shared__ float feats[16 * 32];
    __shared__ float hid[16 * 64];
    __shared__ float lg[16 * 8];
    int tid = threadIdx.x;
    if (tid < 512) {
        int p = tid >> 5, f = tid & 31;
        int py = p >> 2, px = p & 3;
        int k = f & 7, kind = f >> 3;
        float freq = exp2f((float)k) * 3.14159265358979323846f;
        float cy = (py + 0.5f) * 0.25f;
        float cx = (px + 0.5f) * 0.25f;
        float v;
        if (kind == 0)      v = sinf(cy * freq);
        else if (kind == 1) v = cosf(cy * freq);
        else if (kind == 2) v = sinf(cx * freq);
        else                v = cosf(cx * freq);
        feats[p * 32 + f] = v;
    }
    __syncthreads();
    {
        int p = tid >> 6, hh = tid & 63;
        float a = b1[hh];
        for (int f = 0; f < 32; f++) a += feats[p * 32 + f] * w1[f * 64 + hh];
        hid[p * 64 + hh] = a / (1.0f + expf(-a));
    }
    __syncthreads();
    if (tid < 128) {
        int p = tid >> 3, e = tid & 7;
        float a = b2[e];
        for (int hh = 0; hh < 64; hh++) a += hid[p * 64 + hh] * w2[hh * 8 + e];
        lg[p * 8 + e] = a;
    }
    __syncthreads();
    if (tid < 16) {
        float mx = -1e30f;
        for (int e = 0; e < 8; e++) mx = fmaxf(mx, lg[tid * 8 + e]);
        float ex[8], s = 0.f;
        for (int e = 0; e < 8; e++) { ex[e] = expf(lg[tid * 8 + e] - mx); s += ex[e]; }
        float inv = 1.0f / s;
        for (int e = 0; e < 8; e++) g_wts[tid * 8 + e] = ex[e] * inv;
    }
}

// ---------------- expert conv: fp16 mma m16n8k16, block 128oc x 256px -------
// 16 warps = ocw(4: 32oc) x orow(4). grid (hb=16, e*16+b=128). K = 8 chunks x 16c.
#define XA0 0
#define XA1 3168
#define WA0 6336
#define WA1 15552
#define EXPF 24768

extern __shared__ float smem_all[];

__global__ __launch_bounds__(512, 1) void k_expert_mma() {
    int tid = threadIdx.x;
    int wid = tid >> 5, lane = tid & 31;
    int q = lane >> 2, r = lane & 3;
    int ocw = wid & 3, orow = wid >> 2;
    int hb = blockIdx.x;
    int b = blockIdx.y & 15, e = blockIdx.y >> 4;
    unsigned smem_u = (unsigned)__cvta_generic_to_shared(smem_all);

    float acc[2][8][4];
#pragma unroll
    for (int i = 0; i < 2; i++)
#pragma unroll
        for (int j = 0; j < 8; j++)
#pragma unroll
            for (int l = 0; l < 4; l++) acc[i][j][l] = 0.f;

    // zero halo pixels (px 0 and 65) of both X buffers: 32B each, as 8 floats
    if (tid < 192) {
        int bf = tid / 96, t = tid % 96;
        int row = t >> 4, side = (t >> 3) & 1, f = t & 7;
        smem_all[(bf ? XA1 : XA0) + row * 528 + (side ? 65 : 0) * 8 + f] = 0.f;
    }

    auto stage = [&](int chunk, int bf) {
        unsigned sx = smem_u + 4u * (bf ? XA1 : XA0);
        unsigned sw = smem_u + 4u * (bf ? WA1 : WA0);
        const __half* xs = g_xr + (size_t)(b * 8 + chunk) * 65536;
        for (int idx = tid; idx < 768; idx += 512) {
            int row = idx >> 7, f4 = idx & 127;
            int ih = 4 * hb - 1 + row;
            bool v = ((unsigned)ih < 64u);
            cp16(sx + (unsigned)(row * 2112 + 32 + f4 * 16),
                 xs + (size_t)(v ? ih : 0) * 1024 + f4 * 8, v ? 16 : 0);
        }
        const __half* ws = g_wr + (size_t)(e * 8 + chunk) * 18432;
        for (int idx = tid; idx < 2304; idx += 512)
            cp16(sw + idx * 16u, ws + idx * 8, 16);
    };

    stage(0, 0); cp_commit();
    stage(1, 1); cp_commit();

    for (int c = 0; c < 8; c++) {
        cp_wait1();
        __syncthreads();
        int bf = c & 1;
        const char* sX = (const char*)smem_all + 4 * (bf ? XA1 : XA0);
        const char* sW = (const char*)smem_all + 4 * (bf ? WA1 : WA0);
#pragma unroll
        for (int tap = 0; tap < 9; tap++) {
            int dy = tap / 3, dx = tap - dy * 3;
            const char* wp = sW + tap * 4096 + (ocw * 32 + q) * 32 + r * 8;
            uint2 Alo[2], Ahi[2];
#pragma unroll
            for (int mt = 0; mt < 2; mt++) {
                Alo[mt] = *(const uint2*)(wp + mt * 512);
                Ahi[mt] = *(const uint2*)(wp + mt * 512 + 256);
            }
            const char* xp = sX + (orow + dy) * 2112 + (q + dx) * 32 + r * 8;
#pragma unroll
            for (int nt = 0; nt < 8; nt++) {
                uint2 Bv = *(const uint2*)(xp + nt * 256);
                mma16(acc[0][nt], Alo[0].x, Ahi[0].x, Alo[0].y, Ahi[0].y, Bv.x, Bv.y);
                mma16(acc[1][nt], Alo[1].x, Ahi[1].x, Alo[1].y, Ahi[1].y, Bv.x, Bv.y);
            }
        }
        __syncthreads();
        if (c + 2 < 8) stage(c + 2, bf);
        cp_commit();
    }

    // ---- stats: mt-th 16-oc slice of this warp's 32 oc = group ocw*2+mt ----
#pragma unroll
    for (int mt = 0; mt < 2; mt++) {
        float s1 = 0.f, s2 = 0.f;
#pragma unroll
        for (int nt = 0; nt < 8; nt++)
#pragma unroll
            for (int j = 0; j < 4; j++) {
                float v = acc[mt][nt][j];
                s1 += v; s2 += v * v;
            }
#pragma unroll
        for (int off = 16; off > 0; off >>= 1) {
            s1 += __shfl_xor_sync(0xffffffffu, s1, off);
            s2 += __shfl_xor_sync(0xffffffffu, s2, off);
        }
        if (lane == 0) {
            int g = ocw * 2 + mt;
            int slot = (e * NB + b) * 8 + g;
            g_part_exp[(slot * 64 + hb * 4 + orow) * 2 + 0] = s1;
            g_part_exp[(slot * 64 + hb * 4 + orow) * 2 + 1] = s2;
        }
    }

    // ---- output: single fp16 staging pass (128 oc x 256 px, pitch 264) ----
    __half* stg = (__half*)smem_all;
#pragma unroll
    for (int mt = 0; mt < 2; mt++)
#pragma unroll
        for (int nt = 0; nt < 8; nt++) {
            int oc0 = ocw * 32 + mt * 16 + q;
            int px = orow * 64 + nt * 8 + 2 * r;
            *(__half2*)(stg + oc0 * 264 + px) =
                __floats2half2_rn(acc[mt][nt][0], acc[mt][nt][1]);
            *(__half2*)(stg + (oc0 + 8) * 264 + px) =
                __floats2half2_rn(acc[mt][nt][2], acc[mt][nt][3]);
        }
    __syncthreads();
    size_t zbase = (size_t)((e * NB + b) * NC) * HWSZ;
    for (int idx = tid; idx < 4096; idx += 512) {
        int oc = idx >> 5, p8 = (idx & 31) * 8;
        uint4 v = *(const uint4*)(stg + oc * 264 + p8);
        int h = 4 * hb + (p8 >> 6), w = p8 & 63;
        *(uint4*)(g_z + zbase + (size_t)oc * HWSZ + h * 64 + w) = v;
    }
}

// ---------------- finalize stats ----------------
__global__ void k_finalize(int which) {
    const float* part; float* ms; int nper, nslots; float invN;
    if (which == 0)      { part = g_part_exp; ms = g_ms_exp; nper = 64; nslots = 1024; invN = 1.0f / 65536.0f; }
    else if (which == 1) { part = g_part1;    ms = g_ms1;    nper = 32; nslots = 128;  invN = 1.0f / 262144.0f; }
    else if (which == 2) { part = g_part2;    ms = g_ms2;    nper = 64; nslots = 128;  invN = 1.0f / 262144.0f; }
    else                 { part = g_part3;    ms = g_ms3;    nper = 16; nslots = 128;  invN = 1.0f / 16384.0f; }
    int s = blockIdx.x * blockDim.x + threadIdx.x;
    if (s >= nslots) return;
    float s1 = 0.f, s2 = 0.f;
    for (int i = 0; i < nper; i++) {
        s1 += part[(s * nper + i) * 2 + 0];
        s2 += part[(s * nper + i) * 2 + 1];
    }
    float m = s1 * invN;
    float v = s2 * invN - m * m;
    ms[s * 2 + 0] = m;
    ms[s * 2 + 1] = rsqrtf(v + 1e-5f);
}

// ---------------- combine: GN+SiLU+residual+weights -> fp16 permuted --------
__global__ __launch_bounds__(256) void k_combine(const float* __restrict__ x,
                                                 const float* __restrict__ gs,
                                                 const float* __restrict__ gb) {
    int idx = blockIdx.x * 256 + threadIdx.x;   // 524288 = B*8*4096
    int px = idx & 4095, chunk = (idx >> 12) & 7, b = idx >> 15;
    int h = px >> 6, w = px & 63;
    int patch = ((h >> 4) << 2) + (w >> 4);
    float res[16];
#pragma unroll
    for (int j = 0; j < 16; j++) {
        int c = chunk * 16 + kmap(j);
        res[j] = x[((b * 128 + c) << 12) + px];
    }
#pragma unroll
    for (int e = 0; e < 8; e++) {
        float m  = g_ms_exp[(((e * NB + b) * 8) + chunk) * 2 + 0];
        float rs = g_ms_exp[(((e * NB + b) * 8) + chunk) * 2 + 1];
        float wt = g_wts[patch * 8 + e];
#pragma unroll
        for (int j = 0; j < 16; j++) {
            int c = chunk * 16 + kmap(j);
            float zv = __half2float(g_z[((size_t)((e * NB + b) * NC + c)) * HWSZ + px]);
            float t = (zv - m) * rs * gs[e * NC + c] + gb[e * NC + c];
            res[j] += wt * silu_f(t);
        }
    }
    __half2* dst = (__half2*)(g_combp + (size_t)idx * 16);
#pragma unroll
    for (int j = 0; j < 8; j++)
        dst[j] = __floats2half2_rn(res[2 * j], res[2 * j + 1]);
}

// ---------------- pw1: fp16 mma, block 128hc x 128px ----------------
#define P1X0 0
#define P1W0 1024
#define P1X1 2048
#define P1W1 3072
#define RED1 16896
#define PW1F 16928

__global__ __launch_bounds__(256, 2) void k_pw1_mma() {
    int tid = threadIdx.x;
    int wid = tid >> 5, lane = tid & 31;
    int q = lane >> 2, r = lane & 3;
    int ocw = wid >> 1, ph = wid & 1;
    int ht = blockIdx.x, pt = blockIdx.y, b = blockIdx.z;
    unsigned smem_u = (unsigned)__cvta_generic_to_shared(smem_all);

    float acc[2][8][4];
#pragma unroll
    for (int i = 0; i < 2; i++)
#pragma unroll
        for (int j = 0; j < 8; j++)
#pragma unroll
            for (int l = 0; l < 4; l++) acc[i][j][l] = 0.f;

    auto stage = [&](int chunk, int bf) {
        unsigned sxa = smem_u + 4u * (bf ? P1X1 : P1X0);
        unsigned swa = smem_u + 4u * (bf ? P1W1 : P1W0);
        const __half* xsrc = g_combp + ((size_t)(b * 8 + chunk) * 4096 + pt * 128) * 16;
        const __half* wsrc = g_w1r + (ht * 8 + chunk) * 2048;
        cp16(sxa + tid * 16u, xsrc + tid * 8, 16);
        cp16(swa + tid * 16u, wsrc + tid * 8, 16);
    };

    stage(0, 0); cp_commit();
    stage(1, 1); cp_commit();

    for (int k = 0; k < 8; k++) {
        cp_wait1();
        __syncthreads();
        int bf = k & 1;
        const char* sX = (const char*)smem_all + 4 * (bf ? P1X1 : P1X0);
        const char* sW = (const char*)smem_all + 4 * (bf ? P1W1 : P1W0);
        const char* wp = sW + (ocw * 32 + q) * 32 + r * 8;
        uint2 Alo[2], Ahi[2];
#pragma unroll
        for (int mt = 0; mt < 2; mt++) {
            Alo[mt] = *(const uint2*)(wp + mt * 512);
            Ahi[mt] = *(const uint2*)(wp + mt * 512 + 256);
        }
#pragma unroll
        for (int nt = 0; nt < 8; nt++) {
            const char* xp = sX + (ph * 64 + nt * 8 + q) * 32 + r * 8;
            uint2 Bv = *(const uint2*)(xp);
            mma16(acc[0][nt], Alo[0].x, Ahi[0].x, Alo[0].y, Ahi[0].y, Bv.x, Bv.y);
            mma16(acc[1][nt], Alo[1].x, Ahi[1].x, Alo[1].y, Ahi[1].y, Bv.x, Bv.y);
        }
        __syncthreads();
        if (k + 2 < 8) stage(k + 2, bf);
        cp_commit();
    }

    float s1 = 0.f, s2 = 0.f;
#pragma unroll
    for (int i = 0; i < 2; i++)
#pragma unroll
        for (int j = 0; j < 8; j++)
#pragma unroll
            for (int l = 0; l < 4; l++) {
                float v = acc[i][j][l];
                s1 += v; s2 += v * v;
            }
#pragma unroll
    for (int off = 16; off > 0; off >>= 1) {
        s1 += __shfl_xor_sync(0xffffffffu, s1, off);
        s2 += __shfl_xor_sync(0xffffffffu, s2, off);
    }
    float* red = smem_all + RED1;
    if (lane == 0) { red[wid * 2] = s1; red[wid * 2 + 1] = s2; }

    float* stg = smem_all;
#pragma unroll
    for (int mt = 0; mt < 2; mt++)
#pragma unroll
        for (int nt = 0; nt < 8; nt++)
#pragma unroll
            for (int j = 0; j < 4; j++) {
                int hcl = ocw * 32 + mt * 16 + q + 8 * (j >> 1);
                int w = nt * 8 + 2 * r + (j & 1);
                stg[hcl * 132 + ph * 64 + w] = acc[mt][nt][j];
            }
    __syncthreads();
    if (tid < 2) {
        float a = red[tid * 8 + 0] + red[tid * 8 + 2] + red[tid * 8 + 4] + red[tid * 8 + 6];
        float bq = red[tid * 8 + 1] + red[tid * 8 + 3] + red[tid * 8 + 5] + red[tid * 8 + 7];
        int slot = b * 8 + ht * 2 + tid;
        g_part1[(slot * 32 + pt) * 2 + 0] = a;
        g_part1[(slot * 32 + pt) * 2 + 1] = bq;
    }
    for (int idx = tid; idx < 4096; idx += 256) {
        int hcl = idx >> 5, p4 = (idx & 31) * 4;
        float4 v = *(const float4*)(stg + hcl * 132 + p4);
        __half2* dst = (__half2*)(g_h1 + (size_t)(b * NHC + ht * 128 + hcl) * HWSZ +
                                  pt * 128 + p4);
        dst[0] = __floats2half2_rn(v.x, v.y);
        dst[1] = __floats2half2_rn(v.z, v.w);
    }
}

// ---------------- dw: one block per (channel, b); compact stride-2 output ---
__global__ __launch_bounds__(256) void k_dw(const float* __restrict__ w_dw,
                                            const float* __restrict__ s1v,
                                            const float* __restrict__ b1v) {
    __shared__ float sa[4356];
    __shared__ float red[512];
    int tid = threadIdx.x;
    int ch = blockIdx.x, b = blockIdx.y;
    float m  = g_ms1[(b * 8 + (ch >> 6)) * 2 + 0];
    float rs = g_ms1[(b * 8 + (ch >> 6)) * 2 + 1];
    float sc = s1v[ch], bi = b1v[ch];
    for (int idx = tid; idx < 4356; idx += 256) sa[idx] = 0.f;
    __syncthreads();
    const __half* src = g_h1 + (size_t)(b * NHC + ch) * 4096;
    for (int idx = tid; idx < 512; idx += 256) {
        int r = idx >> 3, w8 = (idx & 7) * 8;
        __align__(16) __half raw[8];
        *(uint4*)raw = *(const uint4*)(src + r * 64 + w8);
        float* d = sa + (r + 1) * 66 + 1 + w8;
#pragma unroll
        for (int j = 0; j < 8; j++)
            d[j] = silu_f((__half2float(raw[j]) - m) * rs * sc + bi);
    }
    __syncthreads();
    float wd[9];
#pragma unroll
    for (int j = 0; j < 9; j++) wd[j] = w_dw[ch * 9 + j];
    int r = tid >> 2, w0 = (tid & 3) * 16;
    float s1 = 0.f, s2 = 0.f;
    float* orow = g_h2 + (size_t)(b * NHC + ch) * 1024 + (r >> 1) * 32;
    bool reven = (r & 1) == 0;
#pragma unroll
    for (int k = 0; k < 16; k++) {
        int w = w0 + k;
        float a = 0.f;
#pragma unroll
        for (int dr = 0; dr < 3; dr++)
#pragma unroll
            for (int dt = 0; dt < 3; dt++)
                a += sa[(r + dr) * 66 + w + dt] * wd[dr * 3 + dt];
        s1 += a; s2 += a * a;
        if (reven && !(w & 1)) orow[w >> 1] = a;
    }
    red[tid] = s1; red[256 + tid] = s2;
    __syncthreads();
    for (int st = 128; st > 0; st >>= 1) {
        if (tid < st) { red[tid] += red[tid + st]; red[256 + tid] += red[256 + tid + st]; }
        __syncthreads();
    }
    if (tid == 0) {
        int slot = b * 8 + (ch >> 6);
        g_part2[(slot * 64 + (ch & 63)) * 2 + 0] = red[0];
        g_part2[(slot * 64 + (ch & 63)) * 2 + 1] = red[256];
    }
}

// ---------------- pw2 (reads compact h2) ----------------
__global__ __launch_bounds__(256) void k_pw2(const float* __restrict__ w_pw2,
                                             const float* __restrict__ s2v,
                                             const float* __restrict__ b2v) {
    __shared__ float sA[2048], sW[4096], red[512];
    int tid = threadIdx.x;
    int pt = blockIdx.x, b = blockIdx.y;
    int pg = tid & 15, og = tid >> 4;
    float acc[32];
#pragma unroll
    for (int i = 0; i < 32; i++) acc[i] = 0.f;

    for (int c0 = 0; c0 < 512; c0 += 32) {
        __syncthreads();
        for (int idx = tid; idx < 2048; idx += 256) {
            int kc = idx >> 6, p = idx & 63;
            int hc = c0 + kc;
            float v = g_h2[(size_t)(b * NHC + hc) * 1024 + pt * 64 + p];
            float m  = g_ms2[(b * 8 + (hc >> 6)) * 2 + 0];
            float rr = g_ms2[(b * 8 + (hc >> 6)) * 2 + 1];
            float t = (v - m) * rr * s2v[hc] + b2v[hc];
            sA[idx] = silu_f(t);
        }
        for (int idx = tid; idx < 4096; idx += 256) {
            int kc = idx >> 7, co = idx & 127;
            sW[idx] = w_pw2[co * NHC + c0 + kc];
        }
        __syncthreads();
        for (int kc = 0; kc < 32; kc++) {
            float a0 = sA[kc * 64 + 4 * pg + 0];
            float a1 = sA[kc * 64 + 4 * pg + 1];
            float a2 = sA[kc * 64 + 4 * pg + 2];
            float a3 = sA[kc * 64 + 4 * pg + 3];
#pragma unroll
            for (int l = 0; l < 8; l++) {
                float wv = sW[kc * 128 + 8 * og + l];
                acc[0 * 8 + l] += a0 * wv;
                acc[1 * 8 + l] += a1 * wv;
                acc[2 * 8 + l] += a2 * wv;
                acc[3 * 8 + l] += a3 * wv;
            }
        }
    }
    float s1 = 0.f, s2 = 0.f;
#pragma unroll
    for (int i = 0; i < 32; i++) { s1 += acc[i]; s2 += acc[i] * acc[i]; }
    red[tid] = s1; red[256 + tid] = s2;
    __syncthreads();
    if ((tid & 31) == 0) {
        float a = 0.f, bq = 0.f;
        for (int i = 0; i < 32; i++) { a += red[tid + i]; bq += red[256 + tid + i]; }
        int g = tid >> 5;
        g_part3[((b * 8 + g) * 16 + pt) * 2 + 0] = a;
        g_part3[((b * 8 + g) * 16 + pt) * 2 + 1] = bq;
    }
#pragma unroll
    for (int k = 0; k < 4; k++) {
        int pi = pt * 64 + 4 * pg + k;
        int ii = pi >> 5, jj = pi & 31;
#pragma unroll
        for (int l = 0; l < 8; l++) {
            int co = 8 * og + l;
            g_h3[((b * NC + co) << 10) + (ii << 5) + jj] = acc[k * 8 + l];
        }
    }
}

// ---------------- final ----------------
__global__ void k_out(float* __restrict__ out,
                      const float* __restrict__ s3v, const float* __restrict__ b3v) {
    int idx = blockIdx.x * 256 + threadIdx.x;
    int co = (idx >> 10) & 127, b = idx >> 17;
    int g = co >> 4;
    float m  = g_ms3[(b * 8 + g) * 2 + 0];
    float rs = g_ms3[(b * 8 + g) * 2 + 1];
    float t = (g_h3[idx] - m) * rs * s3v[co] + b3v[co];
    out[idx] = silu_f(t);
}

// ---------------- launch ----------------
extern "C" void kernel_launch(void* const* d_in, const int* in_sizes, int n_in,
                              void* d_out, int out_size) {
    const float* x      = (const float*)d_in[0];
    const float* w_exp  = (const float*)d_in[1];
    const float* gs_e   = (const float*)d_in[2];
    const float* gb_e   = (const float*)d_in[3];
    const float* w1     = (const float*)d_in[4];
    const float* b1     = (const float*)d_in[5];
    const float* w2     = (const float*)d_in[6];
    const float* b2     = (const float*)d_in[7];
    const float* w_pw1  = (const float*)d_in[8];
    const float* gn1_s  = (const float*)d_in[9];
    const float* gn1_b  = (const float*)d_in[10];
    const float* w_dw   = (const float*)d_in[11];
    const float* gn2_s  = (const float*)d_in[12];
    const float* gn2_b  = (const float*)d_in[13];
    const float* w_pw2  = (const float*)d_in[14];
    const float* gn3_s  = (const float*)d_in[15];
    const float* gn3_b  = (const float*)d_in[16];
    float* out = (float*)d_out;

    static bool attr_done = false;
    if (!attr_done) {
        cudaFuncSetAttribute(k_expert_mma, cudaFuncAttributeMaxDynamicSharedMemorySize,
                             EXPF * 4);
        cudaFuncSetAttribute(k_pw1_mma, cudaFuncAttributeMaxDynamicSharedMemorySize,
                             PW1F * 4);
        attr_done = true;
    }

    // expert at launch index 3 so ncu's fixed sample lands on it
    k_xform_x<<<2048, 256>>>(x);
    k_xform_w<<<288, 256>>>(w_exp);
    k_router<<<1, 1024>>>(w1, b1, w2, b2);
    k_expert_mma<<<dim3(16, 128), 512, EXPF * 4>>>();
    k_xform_w1<<<16, 256>>>(w_pw1);
    k_finalize<<<4, 256>>>(0);
    k_combine<<<2048, 256>>>(x, gs_e, gb_e);
    k_pw1_mma<<<dim3(4, 32, 16), 256, PW1F * 4>>>();
    k_finalize<<<4, 256>>>(1);
    k_dw<<<dim3(512, 16), 256>>>(w_dw, gn1_s, gn1_b);
    k_finalize<<<4, 256>>>(2);
    k_pw2<<<dim3(16, 16), 256>>>(w_pw2, gn2_s, gn2_b);
    k_finalize<<<4, 256>>>(3);
    k_out<<<8192, 256>>>(out, gn3_s, gn3_b);
}

// round 10
// speedup vs baseline: 1.0399x; 1.0399x over previous
#include <cuda_runtime.h>
#include <cuda_fp16.h>
#include <math.h>

// ---------------- problem constants ----------------
#define NB   16
#define NC   128
#define NHC  512
#define HWSZ 4096

// ---------------- scratch ----------------
__device__ __half g_z[67108864];     // [E*B][C][HW] expert conv raw (fp16)
__device__ __half g_combp[8388608];  // [B][chunk8][px4096][16kp] fp16
__device__ __half g_h1[33554432];
__device__ float  g_h2[8388608];     // COMPACT [B][HC][32][32]
__device__ float  g_h3[2097152];
__device__ float  g_wts[128];
__device__ __half g_xr[8388608];     // [B][chunk8][h][w][16kp]
__device__ __half g_wr[1179648];     // [E][chunk8][tap9][oc128][16kp]
__device__ __half g_w1r[65536];      // [ht4][chunk8][hcl128][16kp]
__device__ float g_part_exp[1024 * 64 * 2];
__device__ float g_ms_exp[1024 * 2];
__device__ float g_part1[128 * 32 * 2];
__device__ float g_ms1[128 * 2];
__device__ float g_part2[128 * 64 * 2];
__device__ float g_ms2[128 * 2];
__device__ float g_part3[128 * 16 * 2];
__device__ float g_ms3[128 * 2];

__device__ __forceinline__ float silu_f(float x) {
    return x / (1.0f + __expf(-x));
}
// permuted k index: j in [0,16) -> k, so thread r's 4 contiguous halves are
// k = {2r, 2r+1, 2r+8, 2r+9}
__device__ __forceinline__ int kmap(int j) {
    return ((j >> 2) * 2) + (j & 1) + ((j >> 1) & 1) * 8;
}
__device__ __forceinline__ void cp16(unsigned s, const void* g, int sz) {
    asm volatile("cp.async.cg.shared.global [%0], [%1], 16, %2;\n"
                 :: "r"(s), "l"(g), "r"(sz) : "memory");
}
__device__ __forceinline__ void cp_commit() {
    asm volatile("cp.async.commit_group;\n" ::: "memory");
}
__device__ __forceinline__ void cp_wait1() {
    asm volatile("cp.async.wait_group 1;\n" ::: "memory");
}
__device__ __forceinline__ void mma16(float* c, unsigned a0, unsigned a1, unsigned a2,
                                      unsigned a3, unsigned b0, unsigned b1) {
    asm volatile("mma.sync.aligned.m16n8k16.row.col.f32.f16.f16.f32 "
                 "{%0,%1,%2,%3}, {%4,%5,%6,%7}, {%8,%9}, {%0,%1,%2,%3};"
                 : "+f"(c[0]), "+f"(c[1]), "+f"(c[2]), "+f"(c[3])
                 : "r"(a0), "r"(a1), "r"(a2), "r"(a3), "r"(b0), "r"(b1));
}

// ---------------- transforms (fp16 + permute) ----------
__global__ void k_xform_x(const float* __restrict__ x) {
    int idx = blockIdx.x * 256 + threadIdx.x;   // 524288
    int w = idx & 63, h = (idx >> 6) & 63, chunk = (idx >> 12) & 7, b = idx >> 15;
    __align__(16) __half o[16];
#pragma unroll
    for (int j = 0; j < 16; j++) {
        int c = chunk * 16 + kmap(j);
        o[j] = __float2half(x[((b * 128 + c) << 12) + (h << 6) + w]);
    }
    uint4* dst = (uint4*)(g_xr + (size_t)idx * 16);
    dst[0] = ((uint4*)o)[0];
    dst[1] = ((uint4*)o)[1];
}

__global__ void k_xform_w(const float* __restrict__ w_exp) {
    int idx = blockIdx.x * 256 + threadIdx.x;   // 73728
    int oc = idx & 127;
    int t2 = idx >> 7;
    int tap = t2 % 9, ec = t2 / 9;
    int chunk = ec & 7, e = ec >> 3;
    __align__(16) __half o[16];
#pragma unroll
    for (int j = 0; j < 16; j++) {
        int c = chunk * 16 + kmap(j);
        o[j] = __float2half(w_exp[((e * 128 + oc) * 128 + c) * 9 + tap]);
    }
    uint4* dst = (uint4*)(g_wr + (size_t)idx * 16);
    dst[0] = ((uint4*)o)[0];
    dst[1] = ((uint4*)o)[1];
}

__global__ void k_xform_w1(const float* __restrict__ w_pw1) {
    int idx = blockIdx.x * 256 + threadIdx.x;   // 4096
    int hcl = idx & 127, chunk = (idx >> 7) & 7, ht = idx >> 10;
    __align__(16) __half o[16];
#pragma unroll
    for (int j = 0; j < 16; j++) {
        int c = chunk * 16 + kmap(j);
        o[j] = __float2half(w_pw1[(ht * 128 + hcl) * 128 + c]);
    }
    uint4* dst = (uint4*)(g_w1r + (size_t)idx * 16);
    dst[0] = ((uint4*)o)[0];
    dst[1] = ((uint4*)o)[1];
}

// ---------------- router ----------------
__global__ void k_router(const float* __restrict__ w1, const float* __restrict__ b1,
                         const float* __restrict__ w2, const float* __restrict__ b2) {
    __shared__ float feats[16 * 32];
    __shared__ float hid[16 * 64];
    __shared__ float lg[16 * 8];
    int tid = threadIdx.x;
    if (tid < 512) {
        int p = tid >> 5, f = tid & 31;
        int py = p >> 2, px = p & 3;
        int k = f & 7, kind = f >> 3;
        float freq = exp2f((float)k) * 3.14159265358979323846f;
        float cy = (py + 0.5f) * 0.25f;
        float cx = (px + 0.5f) * 0.25f;
        float v;
        if (kind == 0)      v = sinf(cy * freq);
        else if (kind == 1) v = cosf(cy * freq);
        else if (kind == 2) v = sinf(cx * freq);
        else                v = cosf(cx * freq);
        feats[p * 32 + f] = v;
    }
    __syncthreads();
    {
        int p = tid >> 6, hh = tid & 63;
        float a = b1[hh];
        for (int f = 0; f < 32; f++) a += feats[p * 32 + f] * w1[f * 64 + hh];
        hid[p * 64 + hh] = a / (1.0f + expf(-a));
    }
    __syncthreads();
    if (tid < 128) {
        int p = tid >> 3, e = tid & 7;
        float a = b2[e];
        for (int hh = 0; hh < 64; hh++) a += hid[p * 64 + hh] * w2[hh * 8 + e];
        lg[p * 8 + e] = a;
    }
    __syncthreads();
    if (tid < 16) {
        float mx = -1e30f;
        for (int e = 0; e < 8; e++) mx = fmaxf(mx, lg[tid * 8 + e]);
        float ex[8], s = 0.f;
        for (int e = 0; e < 8; e++) { ex[e] = expf(lg[tid * 8 + e] - mx); s += ex[e]; }
        float inv = 1.0f / s;
        for (int e = 0; e < 8; e++) g_wts[tid * 8 + e] = ex[e] * inv;
    }
}

// ---------------- expert conv: fp16 mma, block 64oc x 256px, 2 CTA/SM -------
// 8 warps = ocw(2: 32oc) x orow(4). grid (hb=16, octile=2, e*16+b=128).
// smem (floats): X bufs 3168 each; W bufs 4608 each (9 tap x 64 oc x 32B).
#define XA0 0
#define XA1 3168
#define WA0 6336
#define WA1 10944
#define EXPF 15552

extern __shared__ float smem_all[];

__global__ __launch_bounds__(256, 2) void k_expert_mma() {
    int tid = threadIdx.x;
    int wid = tid >> 5, lane = tid & 31;
    int q = lane >> 2, r = lane & 3;
    int ocw = wid & 1, orow = wid >> 1;
    int hb = blockIdx.x, octile = blockIdx.y;
    int b = blockIdx.z & 15, e = blockIdx.z >> 4;
    unsigned smem_u = (unsigned)__cvta_generic_to_shared(smem_all);

    float acc[2][8][4];
#pragma unroll
    for (int i = 0; i < 2; i++)
#pragma unroll
        for (int j = 0; j < 8; j++)
#pragma unroll
            for (int l = 0; l < 4; l++) acc[i][j][l] = 0.f;

    // zero halo pixels (px 0 and 65) of both X buffers: 32B each, as 8 floats
    if (tid < 192) {
        int bf = tid / 96, t = tid % 96;
        int row = t >> 4, side = (t >> 3) & 1, f = t & 7;
        smem_all[(bf ? XA1 : XA0) + row * 528 + (side ? 65 : 0) * 8 + f] = 0.f;
    }

    auto stage = [&](int chunk, int bf) {
        unsigned sx = smem_u + 4u * (bf ? XA1 : XA0);
        unsigned sw = smem_u + 4u * (bf ? WA1 : WA0);
        const __half* xs = g_xr + (size_t)(b * 8 + chunk) * 65536;
        for (int idx = tid; idx < 768; idx += 256) {
            int row = idx >> 7, f4 = idx & 127;
            int ih = 4 * hb - 1 + row;
            bool v = ((unsigned)ih < 64u);
            cp16(sx + (unsigned)(row * 2112 + 32 + f4 * 16),
                 xs + (size_t)(v ? ih : 0) * 1024 + f4 * 8, v ? 16 : 0);
        }
        // W: 9 taps x 64 oc (this octile) x 32B = 1152 cp16
        const __half* ws = g_wr + (size_t)(e * 8 + chunk) * 18432 + octile * 1024;
        for (int idx = tid; idx < 1152; idx += 256) {
            int tap = idx >> 7, rem = idx & 127;
            cp16(sw + idx * 16u, ws + (size_t)tap * 2048 + rem * 8, 16);
        }
    };

    stage(0, 0); cp_commit();
    stage(1, 1); cp_commit();

    for (int c = 0; c < 8; c++) {
        cp_wait1();
        __syncthreads();
        int bf = c & 1;
        const char* sX = (const char*)smem_all + 4 * (bf ? XA1 : XA0);
        const char* sW = (const char*)smem_all + 4 * (bf ? WA1 : WA0);
#pragma unroll
        for (int tap = 0; tap < 9; tap++) {
            int dy = tap / 3, dx = tap - dy * 3;
            const char* wp = sW + tap * 2048 + (ocw * 32 + q) * 32 + r * 8;
            uint2 Alo[2], Ahi[2];
#pragma unroll
            for (int mt = 0; mt < 2; mt++) {
                Alo[mt] = *(const uint2*)(wp + mt * 512);
                Ahi[mt] = *(const uint2*)(wp + mt * 512 + 256);
            }
            const char* xp = sX + (orow + dy) * 2112 + (q + dx) * 32 + r * 8;
#pragma unroll
            for (int nt = 0; nt < 8; nt++) {
                uint2 Bv = *(const uint2*)(xp + nt * 256);
                mma16(acc[0][nt], Alo[0].x, Ahi[0].x, Alo[0].y, Ahi[0].y, Bv.x, Bv.y);
                mma16(acc[1][nt], Alo[1].x, Ahi[1].x, Alo[1].y, Ahi[1].y, Bv.x, Bv.y);
            }
        }
        __syncthreads();
        if (c + 2 < 8) stage(c + 2, bf);
        cp_commit();
    }

    // ---- stats: group g = octile*4 + ocw*2 + mt ----
#pragma unroll
    for (int mt = 0; mt < 2; mt++) {
        float s1 = 0.f, s2 = 0.f;
#pragma unroll
        for (int nt = 0; nt < 8; nt++)
#pragma unroll
            for (int j = 0; j < 4; j++) {
                float v = acc[mt][nt][j];
                s1 += v; s2 += v * v;
            }
#pragma unroll
        for (int off = 16; off > 0; off >>= 1) {
            s1 += __shfl_xor_sync(0xffffffffu, s1, off);
            s2 += __shfl_xor_sync(0xffffffffu, s2, off);
        }
        if (lane == 0) {
            int g = octile * 4 + ocw * 2 + mt;
            int slot = (e * NB + b) * 8 + g;
            g_part_exp[(slot * 64 + hb * 4 + orow) * 2 + 0] = s1;
            g_part_exp[(slot * 64 + hb * 4 + orow) * 2 + 1] = s2;
        }
    }

    // ---- output: single fp16 staging pass (64 oc x 256 px, pitch 264) ----
    __half* stg = (__half*)smem_all;
#pragma unroll
    for (int mt = 0; mt < 2; mt++)
#pragma unroll
        for (int nt = 0; nt < 8; nt++) {
            int oc0 = ocw * 32 + mt * 16 + q;
            int px = orow * 64 + nt * 8 + 2 * r;
            *(__half2*)(stg + oc0 * 264 + px) =
                __floats2half2_rn(acc[mt][nt][0], acc[mt][nt][1]);
            *(__half2*)(stg + (oc0 + 8) * 264 + px) =
                __floats2half2_rn(acc[mt][nt][2], acc[mt][nt][3]);
        }
    __syncthreads();
    size_t zbase = (size_t)((e * NB + b) * NC + octile * 64) * HWSZ;
    for (int idx = tid; idx < 2048; idx += 256) {
        int oc = idx >> 5, p8 = (idx & 31) * 8;
        uint4 v = *(const uint4*)(stg + oc * 264 + p8);
        int h = 4 * hb + (p8 >> 6), w = p8 & 63;
        *(uint4*)(g_z + zbase + (size_t)oc * HWSZ + h * 64 + w) = v;
    }
}

// ---------------- finalize stats ----------------
__global__ void k_finalize(int which) {
    const float* part; float* ms; int nper, nslots; float invN;
    if (which == 0)      { part = g_part_exp; ms = g_ms_exp; nper = 64; nslots = 1024; invN = 1.0f / 65536.0f; }
    else if (which == 1) { part = g_part1;    ms = g_ms1;    nper = 32; nslots = 128;  invN = 1.0f / 262144.0f; }
    else if (which == 2) { part = g_part2;    ms = g_ms2;    nper = 64; nslots = 128;  invN = 1.0f / 262144.0f; }
    else                 { part = g_part3;    ms = g_ms3;    nper = 16; nslots = 128;  invN = 1.0f / 16384.0f; }
    int s = blockIdx.x * blockDim.x + threadIdx.x;
    if (s >= nslots) return;
    float s1 = 0.f, s2 = 0.f;
    for (int i = 0; i < nper; i++) {
        s1 += part[(s * nper + i) * 2 + 0];
        s2 += part[(s * nper + i) * 2 + 1];
    }
    float m = s1 * invN;
    float v = s2 * invN - m * m;
    ms[s * 2 + 0] = m;
    ms[s * 2 + 1] = rsqrtf(v + 1e-5f);
}

// ---------------- combine: GN+SiLU+residual+weights -> fp16 permuted --------
__global__ __launch_bounds__(256) void k_combine(const float* __restrict__ x,
                                                 const float* __restrict__ gs,
                                                 const float* __restrict__ gb) {
    int idx = blockIdx.x * 256 + threadIdx.x;   // 524288 = B*8*4096
    int px = idx & 4095, chunk = (idx >> 12) & 7, b = idx >> 15;
    int h = px >> 6, w = px & 63;
    int patch = ((h >> 4) << 2) + (w >> 4);
    float res[16];
#pragma unroll
    for (int j = 0; j < 16; j++) {
        int c = chunk * 16 + kmap(j);
        res[j] = x[((b * 128 + c) << 12) + px];
    }
#pragma unroll
    for (int e = 0; e < 8; e++) {
        float m  = g_ms_exp[(((e * NB + b) * 8) + chunk) * 2 + 0];
        float rs = g_ms_exp[(((e * NB + b) * 8) + chunk) * 2 + 1];
        float wt = g_wts[patch * 8 + e];
#pragma unroll
        for (int j = 0; j < 16; j++) {
            int c = chunk * 16 + kmap(j);
            float zv = __half2float(g_z[((size_t)((e * NB + b) * NC + c)) * HWSZ + px]);
            float t = (zv - m) * rs * gs[e * NC + c] + gb[e * NC + c];
            res[j] += wt * silu_f(t);
        }
    }
    __half2* dst = (__half2*)(g_combp + (size_t)idx * 16);
#pragma unroll
    for (int j = 0; j < 8; j++)
        dst[j] = __floats2half2_rn(res[2 * j], res[2 * j + 1]);
}

// ---------------- pw1: fp16 mma, block 128hc x 128px ----------------
#define P1X0 0
#define P1W0 1024
#define P1X1 2048
#define P1W1 3072
#define RED1 16896
#define PW1F 16928

__global__ __launch_bounds__(256, 2) void k_pw1_mma() {
    int tid = threadIdx.x;
    int wid = tid >> 5, lane = tid & 31;
    int q = lane >> 2, r = lane & 3;
    int ocw = wid >> 1, ph = wid & 1;
    int ht = blockIdx.x, pt = blockIdx.y, b = blockIdx.z;
    unsigned smem_u = (unsigned)__cvta_generic_to_shared(smem_all);

    float acc[2][8][4];
#pragma unroll
    for (int i = 0; i < 2; i++)
#pragma unroll
        for (int j = 0; j < 8; j++)
#pragma unroll
            for (int l = 0; l < 4; l++) acc[i][j][l] = 0.f;

    auto stage = [&](int chunk, int bf) {
        unsigned sxa = smem_u + 4u * (bf ? P1X1 : P1X0);
        unsigned swa = smem_u + 4u * (bf ? P1W1 : P1W0);
        const __half* xsrc = g_combp + ((size_t)(b * 8 + chunk) * 4096 + pt * 128) * 16;
        const __half* wsrc = g_w1r + (ht * 8 + chunk) * 2048;
        cp16(sxa + tid * 16u, xsrc + tid * 8, 16);
        cp16(swa + tid * 16u, wsrc + tid * 8, 16);
    };

    stage(0, 0); cp_commit();
    stage(1, 1); cp_commit();

    for (int k = 0; k < 8; k++) {
        cp_wait1();
        __syncthreads();
        int bf = k & 1;
        const char* sX = (const char*)smem_all + 4 * (bf ? P1X1 : P1X0);
        const char* sW = (const char*)smem_all + 4 * (bf ? P1W1 : P1W0);
        const char* wp = sW + (ocw * 32 + q) * 32 + r * 8;
        uint2 Alo[2], Ahi[2];
#pragma unroll
        for (int mt = 0; mt < 2; mt++) {
            Alo[mt] = *(const uint2*)(wp + mt * 512);
            Ahi[mt] = *(const uint2*)(wp + mt * 512 + 256);
        }
#pragma unroll
        for (int nt = 0; nt < 8; nt++) {
            const char* xp = sX + (ph * 64 + nt * 8 + q) * 32 + r * 8;
            uint2 Bv = *(const uint2*)(xp);
            mma16(acc[0][nt], Alo[0].x, Ahi[0].x, Alo[0].y, Ahi[0].y, Bv.x, Bv.y);
            mma16(acc[1][nt], Alo[1].x, Ahi[1].x, Alo[1].y, Ahi[1].y, Bv.x, Bv.y);
        }
        __syncthreads();
        if (k + 2 < 8) stage(k + 2, bf);
        cp_commit();
    }

    float s1 = 0.f, s2 = 0.f;
#pragma unroll
    for (int i = 0; i < 2; i++)
#pragma unroll
        for (int j = 0; j < 8; j++)
#pragma unroll
            for (int l = 0; l < 4; l++) {
                float v = acc[i][j][l];
                s1 += v; s2 += v * v;
            }
#pragma unroll
    for (int off = 16; off > 0; off >>= 1) {
        s1 += __shfl_xor_sync(0xffffffffu, s1, off);
        s2 += __shfl_xor_sync(0xffffffffu, s2, off);
    }
    float* red = smem_all + RED1;
    if (lane == 0) { red[wid * 2] = s1; red[wid * 2 + 1] = s2; }

    float* stg = smem_all;
#pragma unroll
    for (int mt = 0; mt < 2; mt++)
#pragma unroll
        for (int nt = 0; nt < 8; nt++)
#pragma unroll
            for (int j = 0; j < 4; j++) {
                int hcl = ocw * 32 + mt * 16 + q + 8 * (j >> 1);
                int w = nt * 8 + 2 * r + (j & 1);
                stg[hcl * 132 + ph * 64 + w] = acc[mt][nt][j];
            }
    __syncthreads();
    if (tid < 2) {
        float a = red[tid * 8 + 0] + red[tid * 8 + 2] + red[tid * 8 + 4] + red[tid * 8 + 6];
        float bq = red[tid * 8 + 1] + red[tid * 8 + 3] + red[tid * 8 + 5] + red[tid * 8 + 7];
        int slot = b * 8 + ht * 2 + tid;
        g_part1[(slot * 32 + pt) * 2 + 0] = a;
        g_part1[(slot * 32 + pt) * 2 + 1] = bq;
    }
    for (int idx = tid; idx < 4096; idx += 256) {
        int hcl = idx >> 5, p4 = (idx & 31) * 4;
        float4 v = *(const float4*)(stg + hcl * 132 + p4);
        __half2* dst = (__half2*)(g_h1 + (size_t)(b * NHC + ht * 128 + hcl) * HWSZ +
                                  pt * 128 + p4);
        dst[0] = __floats2half2_rn(v.x, v.y);
        dst[1] = __floats2half2_rn(v.z, v.w);
    }
}

// ---------------- dw: one block per (channel, b); compact stride-2 output ---
__global__ __launch_bounds__(256) void k_dw(const float* __restrict__ w_dw,
                                            const float* __restrict__ s1v,
                                            const float* __restrict__ b1v) {
    __shared__ float sa[4356];
    __shared__ float red[512];
    int tid = threadIdx.x;
    int ch = blockIdx.x, b = blockIdx.y;
    float m  = g_ms1[(b * 8 + (ch >> 6)) * 2 + 0];
    float rs = g_ms1[(b * 8 + (ch >> 6)) * 2 + 1];
    float sc = s1v[ch], bi = b1v[ch];
    for (int idx = tid; idx < 4356; idx += 256) sa[idx] = 0.f;
    __syncthreads();
    const __half* src = g_h1 + (size_t)(b * NHC + ch) * 4096;
    for (int idx = tid; idx < 512; idx += 256) {
        int r = idx >> 3, w8 = (idx & 7) * 8;
        __align__(16) __half raw[8];
        *(uint4*)raw = *(const uint4*)(src + r * 64 + w8);
        float* d = sa + (r + 1) * 66 + 1 + w8;
#pragma unroll
        for (int j = 0; j < 8; j++)
            d[j] = silu_f((__half2float(raw[j]) - m) * rs * sc + bi);
    }
    __syncthreads();
    float wd[9];
#pragma unroll
    for (int j = 0; j < 9; j++) wd[j] = w_dw[ch * 9 + j];
    int r = tid >> 2, w0 = (tid & 3) * 16;
    float s1 = 0.f, s2 = 0.f;
    float* orow = g_h2 + (size_t)(b * NHC + ch) * 1024 + (r >> 1) * 32;
    bool reven = (r & 1) == 0;
#pragma unroll
    for (int k = 0; k < 16; k++) {
        int w = w0 + k;
        float a = 0.f;
#pragma unroll
        for (int dr = 0; dr < 3; dr++)
#pragma unroll
            for (int dt = 0; dt < 3; dt++)
                a += sa[(r + dr) * 66 + w + dt] * wd[dr * 3 + dt];
        s1 += a; s2 += a * a;
        if (reven && !(w & 1)) orow[w >> 1] = a;
    }
    red[tid] = s1; red[256 + tid] = s2;
    __syncthreads();
    for (int st = 128; st > 0; st >>= 1) {
        if (tid < st) { red[tid] += red[tid + st]; red[256 + tid] += red[256 + tid + st]; }
        __syncthreads();
    }
    if (tid == 0) {
        int slot = b * 8 + (ch >> 6);
        g_part2[(slot * 64 + (ch & 63)) * 2 + 0] = red[0];
        g_part2[(slot * 64 + (ch & 63)) * 2 + 1] = red[256];
    }
}

// ---------------- pw2 (reads compact h2) ----------------
__global__ __launch_bounds__(256) void k_pw2(const float* __restrict__ w_pw2,
                                             const float* __restrict__ s2v,
                                             const float* __restrict__ b2v) {
    __shared__ float sA[2048], sW[4096], red[512];
    int tid = threadIdx.x;
    int pt = blockIdx.x, b = blockIdx.y;
    int pg = tid & 15, og = tid >> 4;
    float acc[32];
#pragma unroll
    for (int i = 0; i < 32; i++) acc[i] = 0.f;

    for (int c0 = 0; c0 < 512; c0 += 32) {
        __syncthreads();
        for (int idx = tid; idx < 2048; idx += 256) {
            int kc = idx >> 6, p = idx & 63;
            int hc = c0 + kc;
            float v = g_h2[(size_t)(b * NHC + hc) * 1024 + pt * 64 + p];
            float m  = g_ms2[(b * 8 + (hc >> 6)) * 2 + 0];
            float rr = g_ms2[(b * 8 + (hc >> 6)) * 2 + 1];
            float t = (v - m) * rr * s2v[hc] + b2v[hc];
            sA[idx] = silu_f(t);
        }
        for (int idx = tid; idx < 4096; idx += 256) {
            int kc = idx >> 7, co = idx & 127;
            sW[idx] = w_pw2[co * NHC + c0 + kc];
        }
        __syncthreads();
        for (int kc = 0; kc < 32; kc++) {
            float a0 = sA[kc * 64 + 4 * pg + 0];
            float a1 = sA[kc * 64 + 4 * pg + 1];
            float a2 = sA[kc * 64 + 4 * pg + 2];
            float a3 = sA[kc * 64 + 4 * pg + 3];
#pragma unroll
            for (int l = 0; l < 8; l++) {
                float wv = sW[kc * 128 + 8 * og + l];
                acc[0 * 8 + l] += a0 * wv;
                acc[1 * 8 + l] += a1 * wv;
                acc[2 * 8 + l] += a2 * wv;
                acc[3 * 8 + l] += a3 * wv;
            }
        }
    }
    float s1 = 0.f, s2 = 0.f;
#pragma unroll
    for (int i = 0; i < 32; i++) { s1 += acc[i]; s2 += acc[i] * acc[i]; }
    red[tid] = s1; red[256 + tid] = s2;
    __syncthreads();
    if ((tid & 31) == 0) {
        float a = 0.f, bq = 0.f;
        for (int i = 0; i < 32; i++) { a += red[tid + i]; bq += red[256 + tid + i]; }
        int g = tid >> 5;
        g_part3[((b * 8 + g) * 16 + pt) * 2 + 0] = a;
        g_part3[((b * 8 + g) * 16 + pt) * 2 + 1] = bq;
    }
#pragma unroll
    for (int k = 0; k < 4; k++) {
        int pi = pt * 64 + 4 * pg + k;
        int ii = pi >> 5, jj = pi & 31;
#pragma unroll
        for (int l = 0; l < 8; l++) {
            int co = 8 * og + l;
            g_h3[((b * NC + co) << 10) + (ii << 5) + jj] = acc[k * 8 + l];
        }
    }
}

// ---------------- final ----------------
__global__ void k_out(float* __restrict__ out,
                      const float* __restrict__ s3v, const float* __restrict__ b3v) {
    int idx = blockIdx.x * 256 + threadIdx.x;
    int co = (idx >> 10) & 127, b = idx >> 17;
    int g = co >> 4;
    float m  = g_ms3[(b * 8 + g) * 2 + 0];
    float rs = g_ms3[(b * 8 + g) * 2 + 1];
    float t = (g_h3[idx] - m) * rs * s3v[co] + b3v[co];
    out[idx] = silu_f(t);
}

// ---------------- launch ----------------
extern "C" void kernel_launch(void* const* d_in, const int* in_sizes, int n_in,
                              void* d_out, int out_size) {
    const float* x      = (const float*)d_in[0];
    const float* w_exp  = (const float*)d_in[1];
    const float* gs_e   = (const float*)d_in[2];
    const float* gb_e   = (const float*)d_in[3];
    const float* w1     = (const float*)d_in[4];
    const float* b1     = (const float*)d_in[5];
    const float* w2     = (const float*)d_in[6];
    const float* b2     = (const float*)d_in[7];
    const float* w_pw1  = (const float*)d_in[8];
    const float* gn1_s  = (const float*)d_in[9];
    const float* gn1_b  = (const float*)d_in[10];
    const float* w_dw   = (const float*)d_in[11];
    const float* gn2_s  = (const float*)d_in[12];
    const float* gn2_b  = (const float*)d_in[13];
    const float* w_pw2  = (const float*)d_in[14];
    const float* gn3_s  = (const float*)d_in[15];
    const float* gn3_b  = (const float*)d_in[16];
    float* out = (float*)d_out;

    static bool attr_done = false;
    if (!attr_done) {
        cudaFuncSetAttribute(k_expert_mma, cudaFuncAttributeMaxDynamicSharedMemorySize,
                             EXPF * 4);
        cudaFuncSetAttribute(k_pw1_mma, cudaFuncAttributeMaxDynamicSharedMemorySize,
                             PW1F * 4);
        attr_done = true;
    }

    // expert at launch index 3 so ncu's fixed sample lands on it
    k_xform_x<<<2048, 256>>>(x);
    k_xform_w<<<288, 256>>>(w_exp);
    k_router<<<1, 1024>>>(w1, b1, w2, b2);
    k_expert_mma<<<dim3(16, 2, 128), 256, EXPF * 4>>>();
    k_xform_w1<<<16, 256>>>(w_pw1);
    k_finalize<<<4, 256>>>(0);
    k_combine<<<2048, 256>>>(x, gs_e, gb_e);
    k_pw1_mma<<<dim3(4, 32, 16), 256, PW1F * 4>>>();
    k_finalize<<<4, 256>>>(1);
    k_dw<<<dim3(512, 16), 256>>>(w_dw, gn1_s, gn1_b);
    k_finalize<<<4, 256>>>(2);
    k_pw2<<<dim3(16, 16), 256>>>(w_pw2, gn2_s, gn2_b);
    k_finalize<<<4, 256>>>(3);
    k_out<<<8192, 256>>>(out, gn3_s, gn3_b);
}

// round 11
// speedup vs baseline: 1.1961x; 1.1502x over previous
#include <cuda_runtime.h>
#include <cuda_fp16.h>
#include <math.h>

// ---------------- problem constants ----------------
#define NB   16
#define NC   128
#define NHC  512
#define HWSZ 4096

// ---------------- scratch ----------------
__device__ __half g_z[67108864];     // [E*B][C][HW] expert conv raw (fp16)
__device__ __half g_combp[8388608];  // [B][chunk8][px4096][16kp] fp16 (reused by norm2)
__device__ __half g_h1[33554432];
__device__ __half g_h2[8388608];     // COMPACT [B][HC][32][32] fp16
__device__ float  g_h3[2097152];
__device__ float  g_wts[128];
__device__ __half g_xr[8388608];     // [B][chunk8][h][w][16kp]
__device__ __half g_wr[1179648];     // [E][chunk8][tap9][oc128][16kp]
__device__ __half g_w1r[65536];      // [ht4][chunk8][hcl128][16kp]
__device__ __half g_w2r[65536];      // [chunk32][co128][16kp]
__device__ float g_part_exp[1024 * 64 * 2];
__device__ float g_ms_exp[1024 * 2];
__device__ float g_part1[128 * 32 * 2];
__device__ float g_ms1[128 * 2];
__device__ float g_part2[128 * 64 * 2];
__device__ float g_ms2[128 * 2];
__device__ float g_part3[128 * 16 * 2];
__device__ float g_ms3[128 * 2];

__device__ __forceinline__ float silu_f(float x) {
    return x / (1.0f + __expf(-x));
}
// permuted k index: j in [0,16) -> k, so thread r's 4 contiguous halves are
// k = {2r, 2r+1, 2r+8, 2r+9}
__device__ __forceinline__ int kmap(int j) {
    return ((j >> 2) * 2) + (j & 1) + ((j >> 1) & 1) * 8;
}
__device__ __forceinline__ void cp16(unsigned s, const void* g, int sz) {
    asm volatile("cp.async.cg.shared.global [%0], [%1], 16, %2;\n"
                 :: "r"(s), "l"(g), "r"(sz) : "memory");
}
__device__ __forceinline__ void cp_commit() {
    asm volatile("cp.async.commit_group;\n" ::: "memory");
}
__device__ __forceinline__ void cp_wait1() {
    asm volatile("cp.async.wait_group 1;\n" ::: "memory");
}
__device__ __forceinline__ void mma16(float* c, unsigned a0, unsigned a1, unsigned a2,
                                      unsigned a3, unsigned b0, unsigned b1) {
    asm volatile("mma.sync.aligned.m16n8k16.row.col.f32.f16.f16.f32 "
                 "{%0,%1,%2,%3}, {%4,%5,%6,%7}, {%8,%9}, {%0,%1,%2,%3};"
                 : "+f"(c[0]), "+f"(c[1]), "+f"(c[2]), "+f"(c[3])
                 : "r"(a0), "r"(a1), "r"(a2), "r"(a3), "r"(b0), "r"(b1));
}

// ---------------- transforms (fp16 + permute) ----------
__global__ void k_xform_x(const float* __restrict__ x) {
    int idx = blockIdx.x * 256 + threadIdx.x;   // 524288
    int w = idx & 63, h = (idx >> 6) & 63, chunk = (idx >> 12) & 7, b = idx >> 15;
    __align__(16) __half o[16];
#pragma unroll
    for (int j = 0; j < 16; j++) {
        int c = chunk * 16 + kmap(j);
        o[j] = __float2half(x[((b * 128 + c) << 12) + (h << 6) + w]);
    }
    uint4* dst = (uint4*)(g_xr + (size_t)idx * 16);
    dst[0] = ((uint4*)o)[0];
    dst[1] = ((uint4*)o)[1];
}

__global__ void k_xform_w(const float* __restrict__ w_exp) {
    int idx = blockIdx.x * 256 + threadIdx.x;   // 73728
    int oc = idx & 127;
    int t2 = idx >> 7;
    int tap = t2 % 9, ec = t2 / 9;
    int chunk = ec & 7, e = ec >> 3;
    __align__(16) __half o[16];
#pragma unroll
    for (int j = 0; j < 16; j++) {
        int c = chunk * 16 + kmap(j);
        o[j] = __float2half(w_exp[((e * 128 + oc) * 128 + c) * 9 + tap]);
    }
    uint4* dst = (uint4*)(g_wr + (size_t)idx * 16);
    dst[0] = ((uint4*)o)[0];
    dst[1] = ((uint4*)o)[1];
}

__global__ void k_xform_w1(const float* __restrict__ w_pw1) {
    int idx = blockIdx.x * 256 + threadIdx.x;   // 4096
    int hcl = idx & 127, chunk = (idx >> 7) & 7, ht = idx >> 10;
    __align__(16) __half o[16];
#pragma unroll
    for (int j = 0; j < 16; j++) {
        int c = chunk * 16 + kmap(j);
        o[j] = __float2half(w_pw1[(ht * 128 + hcl) * 128 + c]);
    }
    uint4* dst = (uint4*)(g_w1r + (size_t)idx * 16);
    dst[0] = ((uint4*)o)[0];
    dst[1] = ((uint4*)o)[1];
}

__global__ void k_xform_w2(const float* __restrict__ w_pw2) {
    int idx = blockIdx.x * 256 + threadIdx.x;   // 4096
    int co = idx & 127, chunk = idx >> 7;
    __align__(16) __half o[16];
#pragma unroll
    for (int j = 0; j < 16; j++) {
        int hc = chunk * 16 + kmap(j);
        o[j] = __float2half(w_pw2[co * NHC + hc]);
    }
    uint4* dst = (uint4*)(g_w2r + (size_t)idx * 16);
    dst[0] = ((uint4*)o)[0];
    dst[1] = ((uint4*)o)[1];
}

// ---------------- router ----------------
__global__ void k_router(const float* __restrict__ w1, const float* __restrict__ b1,
                         const float* __restrict__ w2, const float* __restrict__ b2) {
    __shared__ float feats[16 * 32];
    __shared__ float hid[16 * 64];
    __shared__ float lg[16 * 8];
    int tid = threadIdx.x;
    if (tid < 512) {
        int p = tid >> 5, f = tid & 31;
        int py = p >> 2, px = p & 3;
        int k = f & 7, kind = f >> 3;
        float freq = exp2f((float)k) * 3.14159265358979323846f;
        float cy = (py + 0.5f) * 0.25f;
        float cx = (px + 0.5f) * 0.25f;
        float v;
        if (kind == 0)      v = sinf(cy * freq);
        else if (kind == 1) v = cosf(cy * freq);
        else if (kind == 2) v = sinf(cx * freq);
        else                v = cosf(cx * freq);
        feats[p * 32 + f] = v;
    }
    __syncthreads();
    {
        int p = tid >> 6, hh = tid & 63;
        float a = b1[hh];
        for (int f = 0; f < 32; f++) a += feats[p * 32 + f] * w1[f * 64 + hh];
        hid[p * 64 + hh] = a / (1.0f + expf(-a));
    }
    __syncthreads();
    if (tid < 128) {
        int p = tid >> 3, e = tid & 7;
        float a = b2[e];
        for (int hh = 0; hh < 64; hh++) a += hid[p * 64 + hh] * w2[hh * 8 + e];
        lg[p * 8 + e] = a;
    }
    __syncthreads();
    if (tid < 16) {
        float mx = -1e30f;
        for (int e = 0; e < 8; e++) mx = fmaxf(mx, lg[tid * 8 + e]);
        float ex[8], s = 0.f;
        for (int e = 0; e < 8; e++) { ex[e] = expf(lg[tid * 8 + e] - mx); s += ex[e]; }
        float inv = 1.0f / s;
        for (int e = 0; e < 8; e++) g_wts[tid * 8 + e] = ex[e] * inv;
    }
}

// ---------------- expert conv: fp16 mma, block 64oc x 256px, 2 CTA/SM -------
#define XA0 0
#define XA1 3168
#define WA0 6336
#define WA1 10944
#define EXPF 15552

extern __shared__ float smem_all[];

__global__ __launch_bounds__(256, 2) void k_expert_mma() {
    int tid = threadIdx.x;
    int wid = tid >> 5, lane = tid & 31;
    int q = lane >> 2, r = lane & 3;
    int ocw = wid & 1, orow = wid >> 1;
    int hb = blockIdx.x, octile = blockIdx.y;
    int b = blockIdx.z & 15, e = blockIdx.z >> 4;
    unsigned smem_u = (unsigned)__cvta_generic_to_shared(smem_all);

    float acc[2][8][4];
#pragma unroll
    for (int i = 0; i < 2; i++)
#pragma unroll
        for (int j = 0; j < 8; j++)
#pragma unroll
            for (int l = 0; l < 4; l++) acc[i][j][l] = 0.f;

    if (tid < 192) {
        int bf = tid / 96, t = tid % 96;
        int row = t >> 4, side = (t >> 3) & 1, f = t & 7;
        smem_all[(bf ? XA1 : XA0) + row * 528 + (side ? 65 : 0) * 8 + f] = 0.f;
    }

    auto stage = [&](int chunk, int bf) {
        unsigned sx = smem_u + 4u * (bf ? XA1 : XA0);
        unsigned sw = smem_u + 4u * (bf ? WA1 : WA0);
        const __half* xs = g_xr + (size_t)(b * 8 + chunk) * 65536;
        for (int idx = tid; idx < 768; idx += 256) {
            int row = idx >> 7, f4 = idx & 127;
            int ih = 4 * hb - 1 + row;
            bool v = ((unsigned)ih < 64u);
            cp16(sx + (unsigned)(row * 2112 + 32 + f4 * 16),
                 xs + (size_t)(v ? ih : 0) * 1024 + f4 * 8, v ? 16 : 0);
        }
        const __half* ws = g_wr + (size_t)(e * 8 + chunk) * 18432 + octile * 1024;
        for (int idx = tid; idx < 1152; idx += 256) {
            int tap = idx >> 7, rem = idx & 127;
            cp16(sw + idx * 16u, ws + (size_t)tap * 2048 + rem * 8, 16);
        }
    };

    stage(0, 0); cp_commit();
    stage(1, 1); cp_commit();

    for (int c = 0; c < 8; c++) {
        cp_wait1();
        __syncthreads();
        int bf = c & 1;
        const char* sX = (const char*)smem_all + 4 * (bf ? XA1 : XA0);
        const char* sW = (const char*)smem_all + 4 * (bf ? WA1 : WA0);
#pragma unroll
        for (int tap = 0; tap < 9; tap++) {
            int dy = tap / 3, dx = tap - dy * 3;
            const char* wp = sW + tap * 2048 + (ocw * 32 + q) * 32 + r * 8;
            uint2 Alo[2], Ahi[2];
#pragma unroll
            for (int mt = 0; mt < 2; mt++) {
                Alo[mt] = *(const uint2*)(wp + mt * 512);
                Ahi[mt] = *(const uint2*)(wp + mt * 512 + 256);
            }
            const char* xp = sX + (orow + dy) * 2112 + (q + dx) * 32 + r * 8;
#pragma unroll
            for (int nt = 0; nt < 8; nt++) {
                uint2 Bv = *(const uint2*)(xp + nt * 256);
                mma16(acc[0][nt], Alo[0].x, Ahi[0].x, Alo[0].y, Ahi[0].y, Bv.x, Bv.y);
                mma16(acc[1][nt], Alo[1].x, Ahi[1].x, Alo[1].y, Ahi[1].y, Bv.x, Bv.y);
            }
        }
        __syncthreads();
        if (c + 2 < 8) stage(c + 2, bf);
        cp_commit();
    }

#pragma unroll
    for (int mt = 0; mt < 2; mt++) {
        float s1 = 0.f, s2 = 0.f;
#pragma unroll
        for (int nt = 0; nt < 8; nt++)
#pragma unroll
            for (int j = 0; j < 4; j++) {
                float v = acc[mt][nt][j];
                s1 += v; s2 += v * v;
            }
#pragma unroll
        for (int off = 16; off > 0; off >>= 1) {
            s1 += __shfl_xor_sync(0xffffffffu, s1, off);
            s2 += __shfl_xor_sync(0xffffffffu, s2, off);
        }
        if (lane == 0) {
            int g = octile * 4 + ocw * 2 + mt;
            int slot = (e * NB + b) * 8 + g;
            g_part_exp[(slot * 64 + hb * 4 + orow) * 2 + 0] = s1;
            g_part_exp[(slot * 64 + hb * 4 + orow) * 2 + 1] = s2;
        }
    }

    __half* stg = (__half*)smem_all;
#pragma unroll
    for (int mt = 0; mt < 2; mt++)
#pragma unroll
        for (int nt = 0; nt < 8; nt++) {
            int oc0 = ocw * 32 + mt * 16 + q;
            int px = orow * 64 + nt * 8 + 2 * r;
            *(__half2*)(stg + oc0 * 264 + px) =
                __floats2half2_rn(acc[mt][nt][0], acc[mt][nt][1]);
            *(__half2*)(stg + (oc0 + 8) * 264 + px) =
                __floats2half2_rn(acc[mt][nt][2], acc[mt][nt][3]);
        }
    __syncthreads();
    size_t zbase = (size_t)((e * NB + b) * NC + octile * 64) * HWSZ;
    for (int idx = tid; idx < 2048; idx += 256) {
        int oc = idx >> 5, p8 = (idx & 31) * 8;
        uint4 v = *(const uint4*)(stg + oc * 264 + p8);
        int h = 4 * hb + (p8 >> 6), w = p8 & 63;
        *(uint4*)(g_z + zbase + (size_t)oc * HWSZ + h * 64 + w) = v;
    }
}

// ---------------- finalize stats ----------------
__global__ void k_finalize(int which) {
    const float* part; float* ms; int nper, nslots; float invN;
    if (which == 0)      { part = g_part_exp; ms = g_ms_exp; nper = 64; nslots = 1024; invN = 1.0f / 65536.0f; }
    else if (which == 1) { part = g_part1;    ms = g_ms1;    nper = 32; nslots = 128;  invN = 1.0f / 262144.0f; }
    else if (which == 2) { part = g_part2;    ms = g_ms2;    nper = 64; nslots = 128;  invN = 1.0f / 262144.0f; }
    else                 { part = g_part3;    ms = g_ms3;    nper = 16; nslots = 128;  invN = 1.0f / 16384.0f; }
    int s = blockIdx.x * blockDim.x + threadIdx.x;
    if (s >= nslots) return;
    float s1 = 0.f, s2 = 0.f;
    for (int i = 0; i < nper; i++) {
        s1 += part[(s * nper + i) * 2 + 0];
        s2 += part[(s * nper + i) * 2 + 1];
    }
    float m = s1 * invN;
    float v = s2 * invN - m * m;
    ms[s * 2 + 0] = m;
    ms[s * 2 + 1] = rsqrtf(v + 1e-5f);
}

// ---------------- combine ----------------
__global__ __launch_bounds__(256) void k_combine(const float* __restrict__ x,
                                                 const float* __restrict__ gs,
                                                 const float* __restrict__ gb) {
    int idx = blockIdx.x * 256 + threadIdx.x;   // 524288 = B*8*4096
    int px = idx & 4095, chunk = (idx >> 12) & 7, b = idx >> 15;
    int h = px >> 6, w = px & 63;
    int patch = ((h >> 4) << 2) + (w >> 4);
    float res[16];
#pragma unroll
    for (int j = 0; j < 16; j++) {
        int c = chunk * 16 + kmap(j);
        res[j] = x[((b * 128 + c) << 12) + px];
    }
#pragma unroll
    for (int e = 0; e < 8; e++) {
        float m  = g_ms_exp[(((e * NB + b) * 8) + chunk) * 2 + 0];
        float rs = g_ms_exp[(((e * NB + b) * 8) + chunk) * 2 + 1];
        float wt = g_wts[patch * 8 + e];
#pragma unroll
        for (int j = 0; j < 16; j++) {
            int c = chunk * 16 + kmap(j);
            float zv = __half2float(g_z[((size_t)((e * NB + b) * NC + c)) * HWSZ + px]);
            float t = (zv - m) * rs * gs[e * NC + c] + gb[e * NC + c];
            res[j] += wt * silu_f(t);
        }
    }
    __half2* dst = (__half2*)(g_combp + (size_t)idx * 16);
#pragma unroll
    for (int j = 0; j < 8; j++)
        dst[j] = __floats2half2_rn(res[2 * j], res[2 * j + 1]);
}

// ---------------- pw1: fp16 mma, block 128hc x 128px ----------------
#define P1X0 0
#define P1W0 1024
#define P1X1 2048
#define P1W1 3072
#define RED1 16896
#define PW1F 16928

__global__ __launch_bounds__(256, 2) void k_pw1_mma() {
    int tid = threadIdx.x;
    int wid = tid >> 5, lane = tid & 31;
    int q = lane >> 2, r = lane & 3;
    int ocw = wid >> 1, ph = wid & 1;
    int ht = blockIdx.x, pt = blockIdx.y, b = blockIdx.z;
    unsigned smem_u = (unsigned)__cvta_generic_to_shared(smem_all);

    float acc[2][8][4];
#pragma unroll
    for (int i = 0; i < 2; i++)
#pragma unroll
        for (int j = 0; j < 8; j++)
#pragma unroll
            for (int l = 0; l < 4; l++) acc[i][j][l] = 0.f;

    auto stage = [&](int chunk, int bf) {
        unsigned sxa = smem_u + 4u * (bf ? P1X1 : P1X0);
        unsigned swa = smem_u + 4u * (bf ? P1W1 : P1W0);
        const __half* xsrc = g_combp + ((size_t)(b * 8 + chunk) * 4096 + pt * 128) * 16;
        const __half* wsrc = g_w1r + (ht * 8 + chunk) * 2048;
        cp16(sxa + tid * 16u, xsrc + tid * 8, 16);
        cp16(swa + tid * 16u, wsrc + tid * 8, 16);
    };

    stage(0, 0); cp_commit();
    stage(1, 1); cp_commit();

    for (int k = 0; k < 8; k++) {
        cp_wait1();
        __syncthreads();
        int bf = k & 1;
        const char* sX = (const char*)smem_all + 4 * (bf ? P1X1 : P1X0);
        const char* sW = (const char*)smem_all + 4 * (bf ? P1W1 : P1W0);
        const char* wp = sW + (ocw * 32 + q) * 32 + r * 8;
        uint2 Alo[2], Ahi[2];
#pragma unroll
        for (int mt = 0; mt < 2; mt++) {
            Alo[mt] = *(const uint2*)(wp + mt * 512);
            Ahi[mt] = *(const uint2*)(wp + mt * 512 + 256);
        }
#pragma unroll
        for (int nt = 0; nt < 8; nt++) {
            const char* xp = sX + (ph * 64 + nt * 8 + q) * 32 + r * 8;
            uint2 Bv = *(const uint2*)(xp);
            mma16(acc[0][nt], Alo[0].x, Ahi[0].x, Alo[0].y, Ahi[0].y, Bv.x, Bv.y);
            mma16(acc[1][nt], Alo[1].x, Ahi[1].x, Alo[1].y, Ahi[1].y, Bv.x, Bv.y);
        }
        __syncthreads();
        if (k + 2 < 8) stage(k + 2, bf);
        cp_commit();
    }

    float s1 = 0.f, s2 = 0.f;
#pragma unroll
    for (int i = 0; i < 2; i++)
#pragma unroll
        for (int j = 0; j < 8; j++)
#pragma unroll
            for (int l = 0; l < 4; l++) {
                float v = acc[i][j][l];
                s1 += v; s2 += v * v;
            }
#pragma unroll
    for (int off = 16; off > 0; off >>= 1) {
        s1 += __shfl_xor_sync(0xffffffffu, s1, off);
        s2 += __shfl_xor_sync(0xffffffffu, s2, off);
    }
    float* red = smem_all + RED1;
    if (lane == 0) { red[wid * 2] = s1; red[wid * 2 + 1] = s2; }

    float* stg = smem_all;
#pragma unroll
    for (int mt = 0; mt < 2; mt++)
#pragma unroll
        for (int nt = 0; nt < 8; nt++)
#pragma unroll
            for (int j = 0; j < 4; j++) {
                int hcl = ocw * 32 + mt * 16 + q + 8 * (j >> 1);
                int w = nt * 8 + 2 * r + (j & 1);
                stg[hcl * 132 + ph * 64 + w] = acc[mt][nt][j];
            }
    __syncthreads();
    if (tid < 2) {
        float a = red[tid * 8 + 0] + red[tid * 8 + 2] + red[tid * 8 + 4] + red[tid * 8 + 6];
        float bq = red[tid * 8 + 1] + red[tid * 8 + 3] + red[tid * 8 + 5] + red[tid * 8 + 7];
        int slot = b * 8 + ht * 2 + tid;
        g_part1[(slot * 32 + pt) * 2 + 0] = a;
        g_part1[(slot * 32 + pt) * 2 + 1] = bq;
    }
    for (int idx = tid; idx < 4096; idx += 256) {
        int hcl = idx >> 5, p4 = (idx & 31) * 4;
        float4 v = *(const float4*)(stg + hcl * 132 + p4);
        __half2* dst = (__half2*)(g_h1 + (size_t)(b * NHC + ht * 128 + hcl) * HWSZ +
                                  pt * 128 + p4);
        dst[0] = __floats2half2_rn(v.x, v.y);
        dst[1] = __floats2half2_rn(v.z, v.w);
    }
}

// ---------------- dw: compact stride-2 output, fp16 ----------------
__global__ __launch_bounds__(256) void k_dw(const float* __restrict__ w_dw,
                                            const float* __restrict__ s1v,
                                            const float* __restrict__ b1v) {
    __shared__ float sa[4356];
    __shared__ float red[512];
    int tid = threadIdx.x;
    int ch = blockIdx.x, b = blockIdx.y;
    float m  = g_ms1[(b * 8 + (ch >> 6)) * 2 + 0];
    float rs = g_ms1[(b * 8 + (ch >> 6)) * 2 + 1];
    float sc = s1v[ch], bi = b1v[ch];
    for (int idx = tid; idx < 4356; idx += 256) sa[idx] = 0.f;
    __syncthreads();
    const __half* src = g_h1 + (size_t)(b * NHC + ch) * 4096;
    for (int idx = tid; idx < 512; idx += 256) {
        int r = idx >> 3, w8 = (idx & 7) * 8;
        __align__(16) __half raw[8];
        *(uint4*)raw = *(const uint4*)(src + r * 64 + w8);
        float* d = sa + (r + 1) * 66 + 1 + w8;
#pragma unroll
        for (int j = 0; j < 8; j++)
            d[j] = silu_f((__half2float(raw[j]) - m) * rs * sc + bi);
    }
    __syncthreads();
    float wd[9];
#pragma unroll
    for (int j = 0; j < 9; j++) wd[j] = w_dw[ch * 9 + j];
    int r = tid >> 2, w0 = (tid & 3) * 16;
    float s1 = 0.f, s2 = 0.f;
    __half* orow = g_h2 + (size_t)(b * NHC + ch) * 1024 + (r >> 1) * 32;
    bool reven = (r & 1) == 0;
#pragma unroll
    for (int k = 0; k < 16; k++) {
        int w = w0 + k;
        float a = 0.f;
#pragma unroll
        for (int dr = 0; dr < 3; dr++)
#pragma unroll
            for (int dt = 0; dt < 3; dt++)
                a += sa[(r + dr) * 66 + w + dt] * wd[dr * 3 + dt];
        s1 += a; s2 += a * a;
        if (reven && !(w & 1)) orow[w >> 1] = __float2half(a);
    }
    red[tid] = s1; red[256 + tid] = s2;
    __syncthreads();
    for (int st = 128; st > 0; st >>= 1) {
        if (tid < st) { red[tid] += red[tid + st]; red[256 + tid] += red[256 + tid + st]; }
        __syncthreads();
    }
    if (tid == 0) {
        int slot = b * 8 + (ch >> 6);
        g_part2[(slot * 64 + (ch & 63)) * 2 + 0] = red[0];
        g_part2[(slot * 64 + (ch & 63)) * 2 + 1] = red[256];
    }
}

// ---------------- norm2: GN2+SiLU -> pw2 B operand (reuses g_combp) --------
__global__ void k_norm2(const float* __restrict__ s2v, const float* __restrict__ b2v) {
    int idx = blockIdx.x * 256 + threadIdx.x;   // 524288 = B*32*1024
    int px = idx & 1023, chunk = (idx >> 10) & 31, b = idx >> 15;
    __align__(16) __half o[16];
#pragma unroll
    for (int j = 0; j < 16; j++) {
        int hc = chunk * 16 + kmap(j);
        float v = __half2float(g_h2[(size_t)(b * NHC + hc) * 1024 + px]);
        float m  = g_ms2[(b * 8 + (hc >> 6)) * 2 + 0];
        float rr = g_ms2[(b * 8 + (hc >> 6)) * 2 + 1];
        o[j] = __float2half(silu_f((v - m) * rr * s2v[hc] + b2v[hc]));
    }
    uint4* dst = (uint4*)(g_combp + (size_t)idx * 16);
    dst[0] = ((uint4*)o)[0];
    dst[1] = ((uint4*)o)[1];
}

// ---------------- pw2: fp16 mma, block 128co x 64px, K=512 -----------------
__global__ __launch_bounds__(256) void k_pw2_mma() {
    __shared__ __align__(16) float sm[3072];
    int tid = threadIdx.x;
    int wid = tid >> 5, lane = tid & 31;
    int q = lane >> 2, r = lane & 3;
    int pt = blockIdx.x, b = blockIdx.y;
    unsigned smem_u = (unsigned)__cvta_generic_to_shared(sm);

    float acc[8][4];
#pragma unroll
    for (int j = 0; j < 8; j++)
#pragma unroll
        for (int l = 0; l < 4; l++) acc[j][l] = 0.f;

    auto stage = [&](int chunk, int bf) {
        unsigned sx = smem_u + 4u * (bf ? 1536 : 0);
        unsigned sw = smem_u + 4u * (bf ? 2048 : 512);
        const __half* xsrc = g_combp + ((size_t)(b * 32 + chunk) * 1024 + pt * 64) * 16;
        const __half* wsrc = g_w2r + (size_t)chunk * 2048;
        if (tid < 128) cp16(sx + tid * 16u, xsrc + tid * 8, 16);
        cp16(sw + tid * 16u, wsrc + tid * 8, 16);
    };

    stage(0, 0); cp_commit();
    stage(1, 1); cp_commit();

    for (int k = 0; k < 32; k++) {
        cp_wait1();
        __syncthreads();
        int bf = k & 1;
        const char* sX = (const char*)sm + 4 * (bf ? 1536 : 0);
        const char* sW = (const char*)sm + 4 * (bf ? 2048 : 512);
        const char* wp = sW + (wid * 16 + q) * 32 + r * 8;
        uint2 Alo = *(const uint2*)(wp);
        uint2 Ahi = *(const uint2*)(wp + 256);
#pragma unroll
        for (int nt = 0; nt < 8; nt++) {
            const char* xp = sX + (nt * 8 + q) * 32 + r * 8;
            uint2 Bv = *(const uint2*)(xp);
            mma16(acc[nt], Alo.x, Ahi.x, Alo.y, Ahi.y, Bv.x, Bv.y);
        }
        __syncthreads();
        if (k + 2 < 32) stage(k + 2, bf);
        cp_commit();
    }

    // stats: warp wid owns co group wid (16 co)
    float s1 = 0.f, s2 = 0.f;
#pragma unroll
    for (int j = 0; j < 8; j++)
#pragma unroll
        for (int l = 0; l < 4; l++) {
            float v = acc[j][l];
            s1 += v; s2 += v * v;
        }
#pragma unroll
    for (int off = 16; off > 0; off >>= 1) {
        s1 += __shfl_xor_sync(0xffffffffu, s1, off);
        s2 += __shfl_xor_sync(0xffffffffu, s2, off);
    }
    if (lane == 0) {
        g_part3[((b * 8 + wid) * 16 + pt) * 2 + 0] = s1;
        g_part3[((b * 8 + wid) * 16 + pt) * 2 + 1] = s2;
    }

    // store raw h3 (direct; pi = pt*64 + local px indexes the compact 32x32)
#pragma unroll
    for (int nt = 0; nt < 8; nt++)
#pragma unroll
        for (int l = 0; l < 4; l++) {
            int co = wid * 16 + q + 8 * (l >> 1);
            int pi = pt * 64 + nt * 8 + 2 * r + (l & 1);
            g_h3[((b * NC + co) << 10) + pi] = acc[nt][l];
        }
}

// ---------------- final ----------------
__global__ void k_out(float* __restrict__ out,
                      const float* __restrict__ s3v, const float* __restrict__ b3v) {
    int idx = blockIdx.x * 256 + threadIdx.x;
    int co = (idx >> 10) & 127, b = idx >> 17;
    int g = co >> 4;
    float m  = g_ms3[(b * 8 + g) * 2 + 0];
    float rs = g_ms3[(b * 8 + g) * 2 + 1];
    float t = (g_h3[idx] - m) * rs * s3v[co] + b3v[co];
    out[idx] = silu_f(t);
}

// ---------------- launch ----------------
extern "C" void kernel_launch(void* const* d_in, const int* in_sizes, int n_in,
                              void* d_out, int out_size) {
    const float* x      = (const float*)d_in[0];
    const float* w_exp  = (const float*)d_in[1];
    const float* gs_e   = (const float*)d_in[2];
    const float* gb_e   = (const float*)d_in[3];
    const float* w1     = (const float*)d_in[4];
    const float* b1     = (const float*)d_in[5];
    const float* w2     = (const float*)d_in[6];
    const float* b2     = (const float*)d_in[7];
    const float* w_pw1  = (const float*)d_in[8];
    const float* gn1_s  = (const float*)d_in[9];
    const float* gn1_b  = (const float*)d_in[10];
    const float* w_dw   = (const float*)d_in[11];
    const float* gn2_s  = (const float*)d_in[12];
    const float* gn2_b  = (const float*)d_in[13];
    const float* w_pw2  = (const float*)d_in[14];
    const float* gn3_s  = (const float*)d_in[15];
    const float* gn3_b  = (const float*)d_in[16];
    float* out = (float*)d_out;

    static bool attr_done = false;
    if (!attr_done) {
        cudaFuncSetAttribute(k_expert_mma, cudaFuncAttributeMaxDynamicSharedMemorySize,
                             EXPF * 4);
        cudaFuncSetAttribute(k_pw1_mma, cudaFuncAttributeMaxDynamicSharedMemorySize,
                             PW1F * 4);
        attr_done = true;
    }

    // expert at launch index 3 so ncu's fixed sample lands on it
    k_xform_x<<<2048, 256>>>(x);
    k_xform_w<<<288, 256>>>(w_exp);
    k_router<<<1, 1024>>>(w1, b1, w2, b2);
    k_expert_mma<<<dim3(16, 2, 128), 256, EXPF * 4>>>();
    k_xform_w1<<<16, 256>>>(w_pw1);
    k_xform_w2<<<16, 256>>>(w_pw2);
    k_finalize<<<4, 256>>>(0);
    k_combine<<<2048, 256>>>(x, gs_e, gb_e);
    k_pw1_mma<<<dim3(4, 32, 16), 256, PW1F * 4>>>();
    k_finalize<<<4, 256>>>(1);
    k_dw<<<dim3(512, 16), 256>>>(w_dw, gn1_s, gn1_b);
    k_finalize<<<4, 256>>>(2);
    k_norm2<<<2048, 256>>>(gn2_s, gn2_b);
    k_pw2_mma<<<dim3(16, 16), 256>>>();
    k_finalize<<<4, 256>>>(3);
    k_out<<<8192, 256>>>(out, gn3_s, gn3_b);
}